// round 9
// baseline (speedup 1.0000x reference)
#include <cuda_runtime.h>
#include <cstdint>

typedef unsigned long long u64;

#define BATCH 32
#define HID   64
#define CHUNK 2048
#define LOGC  11
#define WIN   256          // head window (ring depth)
#define RPAD  68           // ring row stride in floats (17x16B -> conflict-free)

__device__ __forceinline__ u64 fma2(u64 a, u64 b, u64 c){
    u64 d; asm("fma.rn.f32x2 %0, %1, %2, %3;" : "=l"(d) : "l"(a), "l"(b), "l"(c)); return d;
}
__device__ __forceinline__ u64 add2(u64 a, u64 b){
    u64 d; asm("add.rn.f32x2 %0, %1, %2;" : "=l"(d) : "l"(a), "l"(b)); return d;
}
__device__ __forceinline__ float hsum2(u64 a){
    float lo, hi; asm("mov.b64 {%0,%1}, %2;" : "=f"(lo), "=f"(hi) : "l"(a)); return lo + hi;
}
__device__ __forceinline__ float ex2f(float a){
    float d; asm("ex2.approx.f32 %0, %1;" : "=f"(d) : "f"(a)); return d;
}
__device__ __forceinline__ float rcpf(float a){
    float d; asm("rcp.approx.f32 %0, %1;" : "=f"(d) : "f"(a)); return d;
}

#define NEG_L2E (-1.4426950408889634f)
#define TWO_L2E  2.8853900817779268f

// One CTA per batch row. 256 threads; QUAD (4 lanes) per hidden unit i=tid>>2.
// Lane q owns h[16q:16q+16) and computes r/z/n partials over it (8 FMA2 each,
// 4 LDS.128). shfl_xor butterfly (1,2) completes all three dots on all lanes;
// all lanes run the sigma/tanh tail redundantly; lane q0 stores h, ring, states.
// Head (out = h.w_lin + b + x) fused: computed from a 256-step smem ring every
// WIN steps -> no separate kernel, no gmem re-read of states.
__global__ void __launch_bounds__(256, 1)
gru_kernel(const float* __restrict__ x, const float* __restrict__ w_ih,
           const float* __restrict__ w_hh, const float* __restrict__ b_ih,
           const float* __restrict__ b_hh, const float* __restrict__ w_lin,
           const float* __restrict__ b_lin,
           float* __restrict__ out, float* __restrict__ states, int T)
{
    __shared__ __align__(16) float hbuf[2][HID];
    __shared__ __align__(16) float xs[2][CHUNK];
    __shared__ __align__(16) float ring[WIN * RPAD];
    __shared__ float wsh[HID];

    const int tid = threadIdx.x;
    const int b   = blockIdx.x;
    const int i   = tid >> 2;          // hidden unit
    const int q   = tid & 3;           // quad lane
    const int jo  = q << 4;            // h-quarter offset (16 floats)

    // weight slices: rows i (r), 64+i (z), 128+i (n); 16 floats from col jo
    u64 wr[8], wz[8], wn[8];
    {
        const u64* s0 = (const u64*)(w_hh + (size_t)i * 64 + jo);
        const u64* s1 = (const u64*)(w_hh + (size_t)(64 + i) * 64 + jo);
        const u64* s2 = (const u64*)(w_hh + (size_t)(128 + i) * 64 + jo);
        #pragma unroll
        for (int k = 0; k < 8; k++) { wr[k] = s0[k]; wz[k] = s1[k]; wn[k] = s2[k]; }
    }

    // fused activation constants (per-unit, replicated on all 4 lanes)
    const float wihrL = w_ih[i] * NEG_L2E;
    const float carL  = (b_hh[i] + b_ih[i]) * NEG_L2E;
    const float wihzL = w_ih[64 + i] * NEG_L2E;
    const float cazL  = (b_hh[64 + i] + b_ih[64 + i]) * NEG_L2E;
    const float wihn2 = w_ih[128 + i] * TWO_L2E;
    const float bihn2 = b_ih[128 + i] * TWO_L2E;
    const float bhhn2 = b_hh[128 + i] * TWO_L2E;
    const float bl    = b_lin[0];

    const float* xrow = x + (size_t)b * T;

    if (tid < HID) { hbuf[0][tid] = 0.0f; wsh[tid] = w_lin[tid]; }
    {
        const float4* src = (const float4*)xrow;
        float4* dst = (float4*)xs[0];
        #pragma unroll
        for (int k = 0; k < CHUNK / 4 / 256; k++) dst[tid + k * 256] = src[tid + k * 256];
    }
    __syncthreads();

    float* sout = states + ((size_t)b * T) * HID + i;
    float* outp = out + (size_t)b * T;
    float hprev = 0.0f;
    const int nch = T >> LOGC;

    // one GRU step: read h from HC, write new h to HD; slot = ring index
    auto step = [&](const float* hc, float* hd, float xt, int slot, float* sp) {
        const float xrc = fmaf(xt, wihrL, carL);
        const float xzc = fmaf(xt, wihzL, cazL);
        const float xn2 = fmaf(xt, wihn2, bihn2);

        // load my h-quarter (4 x LDS.128)
        ulonglong2 hv[4];
        const ulonglong2* hs = (const ulonglong2*)(hc + jo);
        #pragma unroll
        for (int k = 0; k < 4; k++) hv[k] = hs[k];

        // r/z/n partials over my quarter (8 FMA2 each, 4 accums)
        u64 r0=0,r1=0,r2=0,r3=0, z0=0,z1=0,z2=0,z3=0, n0=0,n1=0,n2=0,n3=0;
        #pragma unroll
        for (int k = 0; k < 2; k++) {
            ulonglong2 h0 = hv[2*k], h1 = hv[2*k+1];
            r0 = fma2(h0.x, wr[4*k],   r0);  r1 = fma2(h0.y, wr[4*k+1], r1);
            r2 = fma2(h1.x, wr[4*k+2], r2);  r3 = fma2(h1.y, wr[4*k+3], r3);
            z0 = fma2(h0.x, wz[4*k],   z0);  z1 = fma2(h0.y, wz[4*k+1], z1);
            z2 = fma2(h1.x, wz[4*k+2], z2);  z3 = fma2(h1.y, wz[4*k+3], z3);
            n0 = fma2(h0.x, wn[4*k],   n0);  n1 = fma2(h0.y, wn[4*k+1], n1);
            n2 = fma2(h1.x, wn[4*k+2], n2);  n3 = fma2(h1.y, wn[4*k+3], n3);
        }
        float rp = hsum2(add2(add2(r0,r1), add2(r2,r3)));
        float zp = hsum2(add2(add2(z0,z1), add2(z2,z3)));
        float np = hsum2(add2(add2(n0,n1), add2(n2,n3)));

        // butterfly over the quad (independent shfls pipeline)
        rp += __shfl_xor_sync(0xffffffffu, rp, 1);
        zp += __shfl_xor_sync(0xffffffffu, zp, 1);
        np += __shfl_xor_sync(0xffffffffu, np, 1);
        rp += __shfl_xor_sync(0xffffffffu, rp, 2);
        zp += __shfl_xor_sync(0xffffffffu, zp, 2);
        np += __shfl_xor_sync(0xffffffffu, np, 2);

        // tail (redundant on all 4 lanes; thread-local)
        float gr  = rcpf(1.0f + ex2f(fmaf(rp, NEG_L2E, xrc)));   // sigma(r)
        float gz  = rcpf(1.0f + ex2f(fmaf(zp, NEG_L2E, xzc)));   // sigma(z)
        float hn2 = fmaf(np, TWO_L2E, bhhn2);
        float e2  = ex2f(fmaf(gr, hn2, xn2));
        float nv  = fmaf(-2.0f, rcpf(e2 + 1.0f), 1.0f);          // tanh
        float hnew = fmaf(gz, hprev - nv, nv);                   // (1-z)*n + z*h
        hprev = hnew;

        if (q == 0) {
            hd[i] = hnew;
            ring[slot * RPAD + i] = hnew;
            __stcs(sp, hnew);
        }
        __syncthreads();
    };

    for (int c = 0; c < nch; c++) {
        if (c + 1 < nch) {  // prefetch next x chunk
            const float4* src = (const float4*)(xrow + (size_t)(c + 1) * CHUNK);
            float4* dst = (float4*)xs[(c + 1) & 1];
            #pragma unroll
            for (int k = 0; k < CHUNK / 4 / 256; k++) dst[tid + k * 256] = src[tid + k * 256];
        }
        const float* xc = xs[c & 1];
        float* sc = sout + (size_t)c * CHUNK * HID;

        for (int w = 0; w < CHUNK / WIN; w++) {
            const int base = w * WIN;
            for (int tl = 0; tl < WIN; tl += 2) {
                step(hbuf[0], hbuf[1], xc[base + tl],     tl,     sc + (size_t)(base + tl) * HID);
                step(hbuf[1], hbuf[0], xc[base + tl + 1], tl + 1, sc + (size_t)(base + tl + 1) * HID);
            }
            // fused head for this window: out[t] = ring_row . w_lin + b + x[t]
            {
                const float4* rrow = (const float4*)(ring + tid * RPAD);
                float acc = 0.0f;
                #pragma unroll
                for (int k = 0; k < HID / 4; k++) {
                    float4 v = rrow[k];
                    acc = fmaf(v.x, wsh[4*k],   acc);
                    acc = fmaf(v.y, wsh[4*k+1], acc);
                    acc = fmaf(v.z, wsh[4*k+2], acc);
                    acc = fmaf(v.w, wsh[4*k+3], acc);
                }
                int tg = base + tid;
                outp[(size_t)c * CHUNK + tg] = acc + bl + xc[tg];
                __syncthreads();   // ring reuse guard
            }
        }
    }
}

extern "C" void kernel_launch(void* const* d_in, const int* in_sizes, int n_in,
                              void* d_out, int out_size)
{
    const float* x     = (const float*)d_in[0];
    const float* w_ih  = (const float*)d_in[1];
    const float* w_hh  = (const float*)d_in[2];
    const float* b_ih  = (const float*)d_in[3];
    const float* b_hh  = (const float*)d_in[4];
    const float* w_lin = (const float*)d_in[5];
    const float* b_lin = (const float*)d_in[6];

    float* out = (float*)d_out;
    const int BT = in_sizes[0];          // B * T
    const int T  = BT / BATCH;
    float* states = out + BT;            // d_out = [out | states]

    gru_kernel<<<BATCH, 256>>>(x, w_ih, w_hh, b_ih, b_hh, w_lin, b_lin,
                               out, states, T);
}

// round 10
// speedup vs baseline: 1.4149x; 1.4149x over previous
#include <cuda_runtime.h>
#include <cstdint>

typedef unsigned long long u64;

#define BATCH 32
#define HID   64
#define CHUNK 2048
#define LOGC  11
#define WIN   128          // fused-head window (ring depth)
#define RPAD  68           // ring row stride (floats)

__device__ __forceinline__ u64 fma2(u64 a, u64 b, u64 c){
    u64 d; asm("fma.rn.f32x2 %0, %1, %2, %3;" : "=l"(d) : "l"(a), "l"(b), "l"(c)); return d;
}
__device__ __forceinline__ u64 add2(u64 a, u64 b){
    u64 d; asm("add.rn.f32x2 %0, %1, %2;" : "=l"(d) : "l"(a), "l"(b)); return d;
}
__device__ __forceinline__ float hsum2(u64 a){
    float lo, hi; asm("mov.b64 {%0,%1}, %2;" : "=f"(lo), "=f"(hi) : "l"(a)); return lo + hi;
}
__device__ __forceinline__ float ex2f(float a){
    float d; asm("ex2.approx.f32 %0, %1;" : "=f"(d) : "f"(a)); return d;
}
__device__ __forceinline__ float rcpf(float a){
    float d; asm("rcp.approx.f32 %0, %1;" : "=f"(d) : "f"(a)); return d;
}

#define NEG_L2E (-1.4426950408889634f)
#define TWO_L2E  2.8853900817779268f

// One CTA per batch row. 128 threads; pair (2i,2i+1) owns hidden unit i.
// ASYMMETRIC split: lane p=0 computes the FULL r-dot (sigma(r) with no shfl
// on the critical path); lane p=1 computes the FULL z-dot; BOTH lanes compute
// a HALF n-dot combined by one shfl whose latency is hidden under the
// sigma(r) MUFU chain. shfl(gz) is consumed at the last FMA (slack). Only
// lane0 stores h/ring/states. Head fused via WIN-step smem ring.
__global__ void __launch_bounds__(128, 1)
gru_kernel(const float* __restrict__ x, const float* __restrict__ w_ih,
           const float* __restrict__ w_hh, const float* __restrict__ b_ih,
           const float* __restrict__ b_hh, const float* __restrict__ w_lin,
           const float* __restrict__ b_lin,
           float* __restrict__ out, float* __restrict__ states, int T)
{
    __shared__ __align__(16) float hbuf[2][HID];
    __shared__ __align__(16) float xs[2][CHUNK];
    __shared__ __align__(16) float ring[WIN * RPAD];
    __shared__ float wsh[HID];

    const int tid = threadIdx.x;
    const int b   = blockIdx.x;
    const int i   = tid >> 1;
    const int p   = tid & 1;
    const int ia  = i + 64 * p;        // r-row (p=0) or z-row (p=1)
    const int in_ = 128 + i;           // n-row
    const int jo  = 32 * p;            // n half-offset for this lane

    // weights into registers (packed f32x2)
    u64 wa[32];                         // full own-gate row
    {
        const u64* was = (const u64*)(w_hh + (size_t)ia * 64);
        #pragma unroll
        for (int q = 0; q < 32; q++) wa[q] = was[q];
    }
    u64 wn[16];                         // half n-row (cols [32p, 32p+32))
    {
        const u64* wns = (const u64*)(w_hh + (size_t)in_ * 64 + jo);
        #pragma unroll
        for (int q = 0; q < 16; q++) wn[q] = wns[q];
    }

    // fused activation constants
    const float wihaL = w_ih[ia] * NEG_L2E;
    const float caL   = (b_hh[ia] + b_ih[ia]) * NEG_L2E;
    const float wihn2 = w_ih[in_] * TWO_L2E;
    const float bihn2 = b_ih[in_] * TWO_L2E;
    const float bhhn2 = b_hh[in_] * TWO_L2E;
    const float bl    = b_lin[0];

    const float* xrow = x + (size_t)b * T;

    if (tid < HID) { hbuf[0][tid] = 0.0f; wsh[tid] = w_lin[tid]; }
    {
        const float4* src = (const float4*)xrow;
        float4* dst = (float4*)xs[0];
        #pragma unroll
        for (int q = 0; q < CHUNK / 4 / 128; q++) dst[tid + q * 128] = src[tid + q * 128];
    }
    __syncthreads();

    float* sout = states + ((size_t)b * T) * HID + i;
    float* outp = out + (size_t)b * T;
    float hprev = 0.0f;
    const int nch = T >> LOGC;

    auto step = [&](const float* hc, float* hd, float xt, int slot, float* sp) {
        const float xac = fmaf(xt, wihaL, caL);
        const float xn2 = fmaf(xt, wihn2, bihn2);

        // full h for the own-gate dot (16 x LDS.128, warp-uniform broadcast)
        ulonglong2 hv[16];
        const ulonglong2* hs = (const ulonglong2*)hc;
        #pragma unroll
        for (int q = 0; q < 16; q++) hv[q] = hs[q];

        // full 64-dot for own gate (r on lane0 / z on lane1): 8 accums
        u64 a0=0,a1=0,a2=0,a3=0,a4=0,a5=0,a6=0,a7=0;
        #pragma unroll
        for (int q = 0; q < 4; q++) {
            a0 = fma2(hv[4*q].x,   wa[8*q],   a0);
            a1 = fma2(hv[4*q].y,   wa[8*q+1], a1);
            a2 = fma2(hv[4*q+1].x, wa[8*q+2], a2);
            a3 = fma2(hv[4*q+1].y, wa[8*q+3], a3);
            a4 = fma2(hv[4*q+2].x, wa[8*q+4], a4);
            a5 = fma2(hv[4*q+2].y, wa[8*q+5], a5);
            a6 = fma2(hv[4*q+3].x, wa[8*q+6], a6);
            a7 = fma2(hv[4*q+3].y, wa[8*q+7], a7);
        }
        float sa = hsum2(add2(add2(add2(a0,a1),add2(a2,a3)),
                              add2(add2(a4,a5),add2(a6,a7))));
        float ga = rcpf(1.0f + ex2f(fmaf(sa, NEG_L2E, xac)));   // sigma(own gate)
        float gz = __shfl_xor_sync(0xffffffffu, ga, 1);         // z for lane0 (slack)

        // half 32-dot for n (own h-half, loaded directly from smem)
        u64 n0=0,n1=0,n2=0,n3=0;
        const ulonglong2* hsn = (const ulonglong2*)(hc + jo);
        #pragma unroll
        for (int q = 0; q < 4; q++) {
            ulonglong2 h0 = hsn[2*q], h1 = hsn[2*q+1];
            n0 = fma2(h0.x, wn[4*q],   n0);
            n1 = fma2(h0.y, wn[4*q+1], n1);
            n2 = fma2(h1.x, wn[4*q+2], n2);
            n3 = fma2(h1.y, wn[4*q+3], n3);
        }
        float np = hsum2(add2(add2(n0,n1), add2(n2,n3)));
        float sn = np + __shfl_xor_sync(0xffffffffu, np, 1);    // lands ~ with sigma(r)

        // tanh tail (both lanes; real only on lane0 where ga = sigma(r))
        float hn2 = fmaf(sn, TWO_L2E, bhhn2);
        float e2  = ex2f(fmaf(ga, hn2, xn2));
        float nv  = fmaf(-2.0f, rcpf(e2 + 1.0f), 1.0f);
        float hnew = fmaf(gz, hprev - nv, nv);                  // (1-z)*n + z*h
        hprev = hnew;

        if (!p) {
            hd[i] = hnew;
            ring[slot * RPAD + i] = hnew;
            __stcs(sp, hnew);
        }
        __syncthreads();
    };

    for (int c = 0; c < nch; c++) {
        if (c + 1 < nch) {  // prefetch next x chunk (one branch per 2048 steps)
            const float4* src = (const float4*)(xrow + (size_t)(c + 1) * CHUNK);
            float4* dst = (float4*)xs[(c + 1) & 1];
            #pragma unroll
            for (int q = 0; q < CHUNK / 4 / 128; q++) dst[tid + q * 128] = src[tid + q * 128];
        }
        const float* xc = xs[c & 1];
        float* sc = sout + (size_t)c * CHUNK * HID;

        #pragma unroll 1
        for (int w = 0; w < CHUNK / WIN; w++) {
            const int base = w * WIN;
            for (int tl = 0; tl < WIN; tl += 2) {
                step(hbuf[0], hbuf[1], xc[base + tl],     tl,     sc + (size_t)(base + tl) * HID);
                step(hbuf[1], hbuf[0], xc[base + tl + 1], tl + 1, sc + (size_t)(base + tl + 1) * HID);
            }
            // fused head: out[t] = ring_row(t) . w_lin + b + x[t], one row/thread
            {
                const float4* rrow = (const float4*)(ring + tid * RPAD);
                float acc = 0.0f;
                #pragma unroll
                for (int k = 0; k < HID / 4; k++) {
                    float4 v = rrow[k];
                    acc = fmaf(v.x, wsh[4*k],   acc);
                    acc = fmaf(v.y, wsh[4*k+1], acc);
                    acc = fmaf(v.z, wsh[4*k+2], acc);
                    acc = fmaf(v.w, wsh[4*k+3], acc);
                }
                int tg = base + tid;
                outp[(size_t)c * CHUNK + tg] = acc + bl + xc[tg];
                __syncthreads();   // ring reuse guard before next window's writes
            }
        }
    }
}

extern "C" void kernel_launch(void* const* d_in, const int* in_sizes, int n_in,
                              void* d_out, int out_size)
{
    const float* x     = (const float*)d_in[0];
    const float* w_ih  = (const float*)d_in[1];
    const float* w_hh  = (const float*)d_in[2];
    const float* b_ih  = (const float*)d_in[3];
    const float* b_hh  = (const float*)d_in[4];
    const float* w_lin = (const float*)d_in[5];
    const float* b_lin = (const float*)d_in[6];

    float* out = (float*)d_out;
    const int BT = in_sizes[0];          // B * T
    const int T  = BT / BATCH;
    float* states = out + BT;            // d_out = [out | states]

    gru_kernel<<<BATCH, 128>>>(x, w_ih, w_hh, b_ih, b_hh, w_lin, b_lin,
                               out, states, T);
}

// round 11
// speedup vs baseline: 1.4989x; 1.0594x over previous
#include <cuda_runtime.h>
#include <cstdint>

typedef unsigned long long u64;

#define BATCH 32
#define HID   64
#define CHUNK 2048
#define LOGC  11

__device__ __forceinline__ u64 fma2(u64 a, u64 b, u64 c){
    u64 d; asm("fma.rn.f32x2 %0, %1, %2, %3;" : "=l"(d) : "l"(a), "l"(b), "l"(c)); return d;
}
__device__ __forceinline__ u64 add2(u64 a, u64 b){
    u64 d; asm("add.rn.f32x2 %0, %1, %2;" : "=l"(d) : "l"(a), "l"(b)); return d;
}
__device__ __forceinline__ u64 mul2(u64 a, u64 b){
    u64 d; asm("mul.rn.f32x2 %0, %1, %2;" : "=l"(d) : "l"(a), "l"(b)); return d;
}
__device__ __forceinline__ u64 pack2(float lo, float hi){
    u64 d; asm("mov.b64 %0, {%1, %2};" : "=l"(d) : "f"(lo), "f"(hi)); return d;
}
__device__ __forceinline__ float hsum2(u64 a){
    float lo, hi; asm("mov.b64 {%0,%1}, %2;" : "=f"(lo), "=f"(hi) : "l"(a)); return lo + hi;
}
__device__ __forceinline__ float ex2f(float a){
    float d; asm("ex2.approx.f32 %0, %1;" : "=f"(d) : "f"(a)); return d;
}
__device__ __forceinline__ float rcpf(float a){
    float d; asm("rcp.approx.f32 %0, %1;" : "=f"(d) : "f"(a)); return d;
}

#define NEG_L2E (-1.4426950408889634f)
#define TWO_L2E  2.8853900817779268f

// One CTA per batch row. 128 threads; pair (2i,2i+1) owns hidden unit i.
// Lane p=0: full 64-dot for r; p=1: full 64-dot for z; BOTH lanes: full
// 64-dot for n (duplicated -- FMA issue is free at 26% issue utilization;
// only chain latency matters). Only z crosses lanes (consumed at the last
// FMA, slack-hidden). Chain surgery vs R7:
//  - weights pre-scaled by -log2e (gates) / 2log2e (n) in the prologue,
//    accumulators initialized with the x/bias terms -> the reduce emits the
//    ex2 argument directly (2 FMAs off the chain),
//  - hnew = A + (2z-2)*R with A,2z-2 computed off-chain (1 FMA off the chain).
__global__ void __launch_bounds__(128, 1)
gru_kernel(const float* __restrict__ x, const float* __restrict__ w_ih,
           const float* __restrict__ w_hh, const float* __restrict__ b_ih,
           const float* __restrict__ b_hh, float* __restrict__ states, int T)
{
    __shared__ __align__(16) float hbuf[2][HID];
    __shared__ __align__(16) float xs[2][CHUNK];

    const int tid = threadIdx.x;
    const int b   = blockIdx.x;
    const int i   = tid >> 1;
    const int p   = tid & 1;
    const int ia  = i + 64 * p;        // r-row (p=0) or z-row (p=1)
    const int in_ = 128 + i;           // n-row

    // weights into registers, PRE-SCALED (packed f32x2)
    u64 wa[32];                         // own-gate row * (-log2e)
    {
        const u64 s = pack2(NEG_L2E, NEG_L2E);
        const u64* was = (const u64*)(w_hh + (size_t)ia * 64);
        #pragma unroll
        for (int q = 0; q < 32; q++) wa[q] = mul2(was[q], s);
    }
    u64 wn[32];                         // full n-row * (2*log2e)
    {
        const u64 s = pack2(TWO_L2E, TWO_L2E);
        const u64* wns = (const u64*)(w_hh + (size_t)in_ * 64);
        #pragma unroll
        for (int q = 0; q < 32; q++) wn[q] = mul2(wns[q], s);
    }

    // fused activation constants
    const float wihaL = w_ih[ia] * NEG_L2E;
    const float caL   = (b_hh[ia] + b_ih[ia]) * NEG_L2E;
    const float wihn2 = w_ih[in_] * TWO_L2E;
    const float bihn2 = b_ih[in_] * TWO_L2E;
    const float bhhn2 = b_hh[in_] * TWO_L2E;

    const float* xrow = x + (size_t)b * T;

    if (tid < HID) hbuf[0][tid] = 0.0f;
    {
        const float4* src = (const float4*)xrow;
        float4* dst = (float4*)xs[0];
        #pragma unroll
        for (int q = 0; q < CHUNK / 4 / 128; q++) dst[tid + q * 128] = src[tid + q * 128];
    }
    __syncthreads();

    float* sout = states + ((size_t)b * T) * HID + i;
    float hprev = 0.0f;
    const int nch = T >> LOGC;
    const u64 nb0 = pack2(bhhn2, 0.0f);      // n-acc init (bias pre-added)

    auto step = [&](const float* hc, float* hd, float xt, float* sp) {
        const float xac = fmaf(xt, wihaL, caL);   // -log2e*(x-part of own gate)
        const float xn2 = fmaf(xt, wihn2, bihn2); // 2log2e*(x-part of n)
        const float hm1 = hprev - 1.0f;           // off-chain

        // load h once (16 x LDS.128), reuse for both dots
        ulonglong2 hv[16];
        const ulonglong2* hs = (const ulonglong2*)hc;
        #pragma unroll
        for (int q = 0; q < 16; q++) hv[q] = hs[q];

        // own-gate 64-dot; acc a0 seeded with xac -> reduce yields ex2 arg
        u64 a0 = pack2(xac, 0.0f);
        u64 a1=0,a2=0,a3=0,a4=0,a5=0,a6=0,a7=0;
        #pragma unroll
        for (int q = 0; q < 4; q++) {
            a0 = fma2(hv[4*q].x,   wa[8*q],   a0);
            a1 = fma2(hv[4*q].y,   wa[8*q+1], a1);
            a2 = fma2(hv[4*q+1].x, wa[8*q+2], a2);
            a3 = fma2(hv[4*q+1].y, wa[8*q+3], a3);
            a4 = fma2(hv[4*q+2].x, wa[8*q+4], a4);
            a5 = fma2(hv[4*q+2].y, wa[8*q+5], a5);
            a6 = fma2(hv[4*q+3].x, wa[8*q+6], a6);
            a7 = fma2(hv[4*q+3].y, wa[8*q+7], a7);
        }
        float argA = hsum2(add2(add2(add2(a0,a1),add2(a2,a3)),
                                add2(add2(a4,a5),add2(a6,a7))));
        float ga = rcpf(1.0f + ex2f(argA));              // sigma(own gate)
        float gz = __shfl_xor_sync(0xffffffffu, ga, 1);  // z for lane0 (slack)

        // n 64-dot (duplicated on both lanes); acc seeded with bhhn2
        u64 n0 = nb0;
        u64 n1=0,n2=0,n3=0,n4=0,n5=0,n6=0,n7=0;
        #pragma unroll
        for (int q = 0; q < 4; q++) {
            n0 = fma2(hv[4*q].x,   wn[8*q],   n0);
            n1 = fma2(hv[4*q].y,   wn[8*q+1], n1);
            n2 = fma2(hv[4*q+1].x, wn[8*q+2], n2);
            n3 = fma2(hv[4*q+1].y, wn[8*q+3], n3);
            n4 = fma2(hv[4*q+2].x, wn[8*q+4], n4);
            n5 = fma2(hv[4*q+2].y, wn[8*q+5], n5);
            n6 = fma2(hv[4*q+3].x, wn[8*q+6], n6);
            n7 = fma2(hv[4*q+3].y, wn[8*q+7], n7);
        }
        float hn2 = hsum2(add2(add2(add2(n0,n1),add2(n2,n3)),
                               add2(add2(n4,n5),add2(n6,n7))));  // 2log2e*hn

        // off-chain (ready before R): A = 1 + z(h-1), gzm2 = 2z-2
        float A    = fmaf(gz, hm1, 1.0f);
        float gzm2 = fmaf(2.0f, gz, -2.0f);

        // chain: e2 -> R -> hnew (single FMA tail)
        float e2 = ex2f(fmaf(ga, hn2, xn2));             // exp(2u)
        float R  = rcpf(e2 + 1.0f);
        float hnew = fmaf(gzm2, R, A);                   // (1-z)tanh(u) + z*h
        hprev = hnew;

        if (!p) {
            hd[i] = hnew;
            __stcs(sp, hnew);
        }
        __syncthreads();
    };

    for (int c = 0; c < nch; c++) {
        if (c + 1 < nch) {  // prefetch next x chunk: one branch per 2048 steps
            const float4* src = (const float4*)(xrow + (size_t)(c + 1) * CHUNK);
            float4* dst = (float4*)xs[(c + 1) & 1];
            #pragma unroll
            for (int q = 0; q < CHUNK / 4 / 128; q++) dst[tid + q * 128] = src[tid + q * 128];
        }
        const float* xc = xs[c & 1];
        float* sc = sout + (size_t)c * CHUNK * HID;

        for (int tl = 0; tl < CHUNK; tl += 2) {
            step(hbuf[0], hbuf[1], xc[tl],     sc + (size_t)tl * HID);
            step(hbuf[1], hbuf[0], xc[tl + 1], sc + (size_t)(tl + 1) * HID);
        }
    }
}

// out[n] = dot(states[n,:], w_lin) + b_lin + x[n]
#define HROWS 128
#define HPAD  65
__global__ void __launch_bounds__(128, 4)
head_kernel(const float* __restrict__ st, const float* __restrict__ x,
            const float* __restrict__ wl, const float* __restrict__ bl,
            float* __restrict__ out, int BT)
{
    __shared__ float tile[HROWS * HPAD];
    __shared__ float wsh[HID];

    const int tid = threadIdx.x;
    const size_t row0 = (size_t)blockIdx.x * HROWS;

    if (tid < HID) wsh[tid] = wl[tid];

    const float4* src = (const float4*)(st + row0 * HID);
    #pragma unroll
    for (int q = 0; q < (HROWS * HID / 4) / 128; q++) {
        int f4 = tid + q * 128;
        float4 v = src[f4];
        int flat = f4 * 4;
        int r = flat >> 6;
        int c = flat & 63;
        float* drow = &tile[r * HPAD + c];
        drow[0] = v.x; drow[1] = v.y; drow[2] = v.z; drow[3] = v.w;
    }
    __syncthreads();

    const float* trow = &tile[tid * HPAD];
    float acc = 0.0f;
    #pragma unroll
    for (int k = 0; k < HID; k++) acc = fmaf(trow[k], wsh[k], acc);

    size_t n = row0 + tid;
    out[n] = acc + bl[0] + x[n];
}

extern "C" void kernel_launch(void* const* d_in, const int* in_sizes, int n_in,
                              void* d_out, int out_size)
{
    const float* x     = (const float*)d_in[0];
    const float* w_ih  = (const float*)d_in[1];
    const float* w_hh  = (const float*)d_in[2];
    const float* b_ih  = (const float*)d_in[3];
    const float* b_hh  = (const float*)d_in[4];
    const float* w_lin = (const float*)d_in[5];
    const float* b_lin = (const float*)d_in[6];

    float* out = (float*)d_out;
    const int BT = in_sizes[0];          // B * T
    const int T  = BT / BATCH;
    float* states = out + BT;            // d_out = [out | states]

    gru_kernel<<<BATCH, 128>>>(x, w_ih, w_hh, b_ih, b_hh, states, T);
    head_kernel<<<BT / HROWS, 128>>>(states, x, w_lin, b_lin, out, BT);
}

// round 12
// speedup vs baseline: 1.5667x; 1.0452x over previous
#include <cuda_runtime.h>
#include <cstdint>

typedef unsigned long long u64;

#define BATCH 32
#define HID   64
#define CHUNK 2048
#define LOGC  11

__device__ __forceinline__ u64 fma2(u64 a, u64 b, u64 c){
    u64 d; asm("fma.rn.f32x2 %0, %1, %2, %3;" : "=l"(d) : "l"(a), "l"(b), "l"(c)); return d;
}
__device__ __forceinline__ u64 add2(u64 a, u64 b){
    u64 d; asm("add.rn.f32x2 %0, %1, %2;" : "=l"(d) : "l"(a), "l"(b)); return d;
}
__device__ __forceinline__ u64 mul2(u64 a, u64 b){
    u64 d; asm("mul.rn.f32x2 %0, %1, %2;" : "=l"(d) : "l"(a), "l"(b)); return d;
}
__device__ __forceinline__ u64 pack2(float lo, float hi){
    u64 d; asm("mov.b64 %0, {%1, %2};" : "=l"(d) : "f"(lo), "f"(hi)); return d;
}
__device__ __forceinline__ float hsum2(u64 a){
    float lo, hi; asm("mov.b64 {%0,%1}, %2;" : "=f"(lo), "=f"(hi) : "l"(a)); return lo + hi;
}
__device__ __forceinline__ float ex2f(float a){
    float d; asm("ex2.approx.f32 %0, %1;" : "=f"(d) : "f"(a)); return d;
}
__device__ __forceinline__ float rcpf(float a){
    float d; asm("rcp.approx.f32 %0, %1;" : "=f"(d) : "f"(a)); return d;
}

#define NEG_L2E (-1.4426950408889634f)
#define TWO_L2E  2.8853900817779268f

// One CTA per batch row. 128 threads; pair (2i,2i+1) owns hidden unit i.
// Lane p=0: full 64-dot for r; p=1: full 64-dot for z; BOTH lanes: full
// 64-dot for n (duplicated: FMA issue hides in stall shadows; chain matters).
// Only z crosses lanes (shfl consumed at the final FMA, slack-hidden).
// Post-bar window decongested: 4-step unrolled body computes ALL four steps'
// x-terms up front (xt LDS + fmas happen in earlier steps' stall shadows),
// states pointer advanced additively (no per-step IMAD chain).
__global__ void __launch_bounds__(128, 1)
gru_kernel(const float* __restrict__ x, const float* __restrict__ w_ih,
           const float* __restrict__ w_hh, const float* __restrict__ b_ih,
           const float* __restrict__ b_hh, float* __restrict__ states, int T)
{
    __shared__ __align__(16) float hbuf[2][HID];
    __shared__ __align__(16) float xs[2][CHUNK];

    const int tid = threadIdx.x;
    const int b   = blockIdx.x;
    const int i   = tid >> 1;
    const int p   = tid & 1;
    const int ia  = i + 64 * p;        // r-row (p=0) or z-row (p=1)
    const int in_ = 128 + i;           // n-row

    // weights into registers, PRE-SCALED (packed f32x2)
    u64 wa[32];                         // own-gate row * (-log2e)
    {
        const u64 s = pack2(NEG_L2E, NEG_L2E);
        const u64* was = (const u64*)(w_hh + (size_t)ia * 64);
        #pragma unroll
        for (int q = 0; q < 32; q++) wa[q] = mul2(was[q], s);
    }
    u64 wn[32];                         // full n-row * (2*log2e)
    {
        const u64 s = pack2(TWO_L2E, TWO_L2E);
        const u64* wns = (const u64*)(w_hh + (size_t)in_ * 64);
        #pragma unroll
        for (int q = 0; q < 32; q++) wn[q] = mul2(wns[q], s);
    }

    // fused activation constants
    const float wihaL = w_ih[ia] * NEG_L2E;
    const float caL   = (b_hh[ia] + b_ih[ia]) * NEG_L2E;
    const float wihn2 = w_ih[in_] * TWO_L2E;
    const float bihn2 = b_ih[in_] * TWO_L2E;
    const float bhhn2 = b_hh[in_] * TWO_L2E;

    const float* xrow = x + (size_t)b * T;

    if (tid < HID) hbuf[0][tid] = 0.0f;
    {
        const float4* src = (const float4*)xrow;
        float4* dst = (float4*)xs[0];
        #pragma unroll
        for (int q = 0; q < CHUNK / 4 / 128; q++) dst[tid + q * 128] = src[tid + q * 128];
    }
    __syncthreads();

    float* sp = states + ((size_t)b * T) * HID + i;   // additive pointer
    float hprev = 0.0f;
    const int nch = T >> LOGC;
    const u64 nb0 = pack2(bhhn2, 0.0f);      // n-acc init (bias pre-added)

    // one GRU step; x-terms precomputed by caller
    auto step = [&](const float* hc, float* hd, float xac, float xn2) {
        const float hm1 = hprev - 1.0f;           // off-chain

        // load h once (16 x LDS.128), reuse for both dots
        ulonglong2 hv[16];
        const ulonglong2* hs = (const ulonglong2*)hc;
        #pragma unroll
        for (int q = 0; q < 16; q++) hv[q] = hs[q];

        // own-gate 64-dot; acc a0 seeded with xac -> reduce yields ex2 arg
        u64 a0 = pack2(xac, 0.0f);
        u64 a1=0,a2=0,a3=0,a4=0,a5=0,a6=0,a7=0;
        #pragma unroll
        for (int q = 0; q < 4; q++) {
            a0 = fma2(hv[4*q].x,   wa[8*q],   a0);
            a1 = fma2(hv[4*q].y,   wa[8*q+1], a1);
            a2 = fma2(hv[4*q+1].x, wa[8*q+2], a2);
            a3 = fma2(hv[4*q+1].y, wa[8*q+3], a3);
            a4 = fma2(hv[4*q+2].x, wa[8*q+4], a4);
            a5 = fma2(hv[4*q+2].y, wa[8*q+5], a5);
            a6 = fma2(hv[4*q+3].x, wa[8*q+6], a6);
            a7 = fma2(hv[4*q+3].y, wa[8*q+7], a7);
        }
        float argA = hsum2(add2(add2(add2(a0,a1),add2(a2,a3)),
                                add2(add2(a4,a5),add2(a6,a7))));
        float ga = rcpf(1.0f + ex2f(argA));              // sigma(own gate)
        float gz = __shfl_xor_sync(0xffffffffu, ga, 1);  // z for lane0 (slack)

        // n 64-dot (duplicated on both lanes); acc seeded with bias
        u64 n0 = nb0;
        u64 n1=0,n2=0,n3=0,n4=0,n5=0,n6=0,n7=0;
        #pragma unroll
        for (int q = 0; q < 4; q++) {
            n0 = fma2(hv[4*q].x,   wn[8*q],   n0);
            n1 = fma2(hv[4*q].y,   wn[8*q+1], n1);
            n2 = fma2(hv[4*q+1].x, wn[8*q+2], n2);
            n3 = fma2(hv[4*q+1].y, wn[8*q+3], n3);
            n4 = fma2(hv[4*q+2].x, wn[8*q+4], n4);
            n5 = fma2(hv[4*q+2].y, wn[8*q+5], n5);
            n6 = fma2(hv[4*q+3].x, wn[8*q+6], n6);
            n7 = fma2(hv[4*q+3].y, wn[8*q+7], n7);
        }
        float hn2 = hsum2(add2(add2(add2(n0,n1),add2(n2,n3)),
                               add2(add2(n4,n5),add2(n6,n7))));  // 2log2e*hn

        // off-chain (ready before R): A = 1 + z(h-1), gzm2 = 2z-2
        float A    = fmaf(gz, hm1, 1.0f);
        float gzm2 = fmaf(2.0f, gz, -2.0f);

        // chain: e2 -> R -> hnew (single FMA tail)
        float e2 = ex2f(fmaf(ga, hn2, xn2));
        float R  = rcpf(e2 + 1.0f);
        float hnew = fmaf(gzm2, R, A);                   // (1-z)tanh + z*h
        hprev = hnew;

        if (!p) {
            hd[i] = hnew;
            __stcs(sp, hnew);
        }
        sp += HID;
        __syncthreads();
    };

    for (int c = 0; c < nch; c++) {
        if (c + 1 < nch) {  // prefetch next x chunk: one branch per 2048 steps
            const float4* src = (const float4*)(xrow + (size_t)(c + 1) * CHUNK);
            float4* dst = (float4*)xs[(c + 1) & 1];
            #pragma unroll
            for (int q = 0; q < CHUNK / 4 / 128; q++) dst[tid + q * 128] = src[tid + q * 128];
        }
        const float* xc = xs[c & 1];

        for (int tl = 0; tl < CHUNK; tl += 4) {
            // all four steps' x-terms up front (filled into stall shadows)
            float xt0 = xc[tl],     xt1 = xc[tl + 1];
            float xt2 = xc[tl + 2], xt3 = xc[tl + 3];
            float xa0 = fmaf(xt0, wihaL, caL), xn0 = fmaf(xt0, wihn2, bihn2);
            float xa1 = fmaf(xt1, wihaL, caL), xn1 = fmaf(xt1, wihn2, bihn2);
            float xa2 = fmaf(xt2, wihaL, caL), xn2_ = fmaf(xt2, wihn2, bihn2);
            float xa3 = fmaf(xt3, wihaL, caL), xn3 = fmaf(xt3, wihn2, bihn2);

            step(hbuf[0], hbuf[1], xa0, xn0);
            step(hbuf[1], hbuf[0], xa1, xn1);
            step(hbuf[0], hbuf[1], xa2, xn2_);
            step(hbuf[1], hbuf[0], xa3, xn3);
        }
    }
}

// out[n] = dot(states[n,:], w_lin) + b_lin + x[n]
#define HROWS 128
#define HPAD  65
__global__ void __launch_bounds__(128, 4)
head_kernel(const float* __restrict__ st, const float* __restrict__ x,
            const float* __restrict__ wl, const float* __restrict__ bl,
            float* __restrict__ out, int BT)
{
    __shared__ float tile[HROWS * HPAD];
    __shared__ float wsh[HID];

    const int tid = threadIdx.x;
    const size_t row0 = (size_t)blockIdx.x * HROWS;

    if (tid < HID) wsh[tid] = wl[tid];

    const float4* src = (const float4*)(st + row0 * HID);
    #pragma unroll
    for (int q = 0; q < (HROWS * HID / 4) / 128; q++) {
        int f4 = tid + q * 128;
        float4 v = src[f4];
        int flat = f4 * 4;
        int r = flat >> 6;
        int c = flat & 63;
        float* drow = &tile[r * HPAD + c];
        drow[0] = v.x; drow[1] = v.y; drow[2] = v.z; drow[3] = v.w;
    }
    __syncthreads();

    const float* trow = &tile[tid * HPAD];
    float acc = 0.0f;
    #pragma unroll
    for (int k = 0; k < HID; k++) acc = fmaf(trow[k], wsh[k], acc);

    size_t n = row0 + tid;
    out[n] = acc + bl[0] + x[n];
}

extern "C" void kernel_launch(void* const* d_in, const int* in_sizes, int n_in,
                              void* d_out, int out_size)
{
    const float* x     = (const float*)d_in[0];
    const float* w_ih  = (const float*)d_in[1];
    const float* w_hh  = (const float*)d_in[2];
    const float* b_ih  = (const float*)d_in[3];
    const float* b_hh  = (const float*)d_in[4];
    const float* w_lin = (const float*)d_in[5];
    const float* b_lin = (const float*)d_in[6];

    float* out = (float*)d_out;
    const int BT = in_sizes[0];          // B * T
    const int T  = BT / BATCH;
    float* states = out + BT;            // d_out = [out | states]

    gru_kernel<<<BATCH, 128>>>(x, w_ih, w_hh, b_ih, b_hh, states, T);
    head_kernel<<<BT / HROWS, 128>>>(states, x, w_lin, b_lin, out, BT);
}